// round 1
// baseline (speedup 1.0000x reference)
#include <cuda_runtime.h>
#include <math.h>

#define NELEM 8192

// ---------------- device scratch (no allocations allowed) ----------------
__device__ float g_u[NELEM];          // unnormalized snr weights
__device__ double g_rank_total;       // sum over upper pairs of mask*(ui+uj)*violation
__device__ unsigned int g_rank_count; // count of masked upper pairs
__device__ float g_red[19];
// g_red layout:
// 0 sum_u, 1 sum_u*(p-smoothed)^2, 2 sum_p, 3 sum_t, 4 sum_p2, 5 sum_t2,
// 6 sum_unc, 7 sum_unc2, 8 sum_e, 9 sum_e2, 10 sum_unc*e,
// 11 sum relu(0.01-unc), 12 sum relu(unc-0.5),
// 13 sum relu(-p), 14 sum relu(p-1),
// 15 max_p, 16 max_t, 17 min_p, 18 min_t

__global__ void init_kernel() {
    g_rank_total = 0.0;
    g_rank_count = 0u;
}

// ---------------- O(N) reductions + u precompute (1 block) ----------------
__global__ __launch_bounds__(1024) void reduce_kernel(
    const float* __restrict__ pr, const float* __restrict__ tg,
    const float* __restrict__ un, const float* __restrict__ sn)
{
    float s[15];
#pragma unroll
    for (int k = 0; k < 15; ++k) s[k] = 0.f;
    float mxp = -1e30f, mxt = -1e30f, mnp = 1e30f, mnt = 1e30f;

    for (int i = threadIdx.x; i < NELEM; i += blockDim.x) {
        float pi = pr[i], ti = tg[i], ci = un[i], si = sn[i];
        float u = fmaf(2.f, expf(si * (-1.f / 15.f)), 0.5f);
        g_u[i] = u;
        float sm = fmaf(ti, 0.95f, 0.025f);     // label smoothing
        float d  = pi - sm;
        s[0] += u;
        s[1] += u * d * d;
        s[2] += pi;  s[3] += ti;
        s[4] += pi * pi;  s[5] += ti * ti;
        float e = fminf(fmaxf(fabsf(pi - ti), 0.001f), 1.f);
        s[6] += ci;  s[7] += ci * ci;
        s[8] += e;   s[9] += e * e;  s[10] += ci * e;
        s[11] += fmaxf(0.01f - ci, 0.f);
        s[12] += fmaxf(ci - 0.5f, 0.f);
        s[13] += fmaxf(-pi, 0.f);
        s[14] += fmaxf(pi - 1.f, 0.f);
        mxp = fmaxf(mxp, pi); mxt = fmaxf(mxt, ti);
        mnp = fminf(mnp, pi); mnt = fminf(mnt, ti);
    }

    const unsigned full = 0xffffffffu;
#pragma unroll
    for (int o = 16; o; o >>= 1) {
#pragma unroll
        for (int k = 0; k < 15; ++k) s[k] += __shfl_down_sync(full, s[k], o);
        mxp = fmaxf(mxp, __shfl_down_sync(full, mxp, o));
        mxt = fmaxf(mxt, __shfl_down_sync(full, mxt, o));
        mnp = fminf(mnp, __shfl_down_sync(full, mnp, o));
        mnt = fminf(mnt, __shfl_down_sync(full, mnt, o));
    }

    __shared__ float sh[32][19];
    int wid = threadIdx.x >> 5, lane = threadIdx.x & 31;
    if (lane == 0) {
#pragma unroll
        for (int k = 0; k < 15; ++k) sh[wid][k] = s[k];
        sh[wid][15] = mxp; sh[wid][16] = mxt; sh[wid][17] = mnp; sh[wid][18] = mnt;
    }
    __syncthreads();
    if (threadIdx.x == 0) {
        float acc[19];
#pragma unroll
        for (int k = 0; k < 19; ++k) acc[k] = sh[0][k];
        for (int w = 1; w < 32; ++w) {
#pragma unroll
            for (int k = 0; k < 15; ++k) acc[k] += sh[w][k];
            acc[15] = fmaxf(acc[15], sh[w][15]);
            acc[16] = fmaxf(acc[16], sh[w][16]);
            acc[17] = fminf(acc[17], sh[w][17]);
            acc[18] = fminf(acc[18], sh[w][18]);
        }
#pragma unroll
        for (int k = 0; k < 19; ++k) g_red[k] = acc[k];
    }
}

// ---------------- O(N^2) ranking kernel (dominant) ----------------
constexpr int ITILE  = 128;   // i per block (== blockDim.x)
constexpr int JCHUNK = 512;   // j per block

__global__ __launch_bounds__(ITILE) void rank_kernel(
    const float* __restrict__ pr, const float* __restrict__ tg)
{
    __shared__ float sh_t[JCHUNK];
    __shared__ float sh_p[JCHUNK];
    __shared__ float sh_u[JCHUNK];

    const int i0 = blockIdx.x * ITILE;
    const int j0 = blockIdx.y * JCHUNK;
    // need some j > i in this tile: max j = j0+JCHUNK-1 must exceed min i = i0
    if (j0 + JCHUNK <= i0 + 1) return;

    for (int k = threadIdx.x; k < JCHUNK; k += ITILE) {
        sh_t[k] = tg[j0 + k];
        sh_p[k] = pr[j0 + k];
        sh_u[k] = g_u[j0 + k];
    }
    __syncthreads();

    const int i  = i0 + threadIdx.x;
    const float ti = tg[i], pi = pr[i], ui = g_u[i];
    float accA = 0.f, accB = 0.f;
    unsigned cnt = 0;

    if (j0 >= i0 + ITILE) {
        // fully above diagonal: no j>i check needed
#pragma unroll 8
        for (int jj = 0; jj < JCHUNK; ++jj) {
            float tj = sh_t[jj], pj = sh_p[jj], uj = sh_u[jj];
            float td  = ti - tj;
            float atd = fabsf(td);
            float pd  = pi - pj;
            float cl  = fminf(fmaxf(atd, 0.1f), 1.0f);
            float spd = (td > 0.f) ? pd : -pd;        // sign(td)*pd
            float v   = fmaxf(fmaf(0.16f, cl, -spd), 0.f); // margin - sign*pd, hinged
            if (atd >= 0.05f) { accA += v; accB = fmaf(uj, v, accB); cnt++; }
        }
    } else {
        // diagonal band: per-pair j>i predicate
#pragma unroll 8
        for (int jj = 0; jj < JCHUNK; ++jj) {
            float tj = sh_t[jj], pj = sh_p[jj], uj = sh_u[jj];
            float td  = ti - tj;
            float atd = fabsf(td);
            float pd  = pi - pj;
            float cl  = fminf(fmaxf(atd, 0.1f), 1.0f);
            float spd = (td > 0.f) ? pd : -pd;
            float v   = fmaxf(fmaf(0.16f, cl, -spd), 0.f);
            bool m = (atd >= 0.05f) && ((j0 + jj) > i);
            if (m) { accA += v; accB = fmaf(uj, v, accB); cnt++; }
        }
    }

    float tot = fmaf(ui, accA, accB);   // sum mask*(ui+uj)*v for this thread

    const unsigned full = 0xffffffffu;
#pragma unroll
    for (int o = 16; o; o >>= 1) {
        tot += __shfl_down_sync(full, tot, o);
        cnt += __shfl_down_sync(full, cnt, o);
    }
    __shared__ float    w_tot[ITILE / 32];
    __shared__ unsigned w_cnt[ITILE / 32];
    int wid = threadIdx.x >> 5;
    if ((threadIdx.x & 31) == 0) { w_tot[wid] = tot; w_cnt[wid] = cnt; }
    __syncthreads();
    if (threadIdx.x == 0) {
        float bt = 0.f; unsigned bc = 0;
#pragma unroll
        for (int w = 0; w < ITILE / 32; ++w) { bt += w_tot[w]; bc += w_cnt[w]; }
        atomicAdd(&g_rank_total, (double)bt);
        atomicAdd(&g_rank_count, bc);
    }
}

// ---------------- finalize (1 thread) ----------------
__global__ void finalize_kernel(float* __restrict__ out, int out_size) {
    const double Nf = (double)NELEM;
    double r[19];
#pragma unroll
    for (int k = 0; k < 19; ++k) r[k] = (double)g_red[k];

    double m = fmax(r[0] / Nf, 1e-6);                    // mean of unnormalized u
    double mse_loss = r[1] / (Nf * m);                   // mean(snr_w*(p-smoothed)^2)

    double rank_loss = 0.0;
    unsigned cnt = g_rank_count;
    if (cnt > 0) rank_loss = (0.5 / m) * g_rank_total / (double)cnt;

    double mean_unc = r[6] / Nf, mean_e = r[8] / Nf;
    double mse_unc  = (r[7] - 2.0 * r[10] + r[9]) / Nf;  // mean((unc-e)^2)
    double cov      = r[10] / Nf - mean_unc * mean_e;
    double std_unc  = fmax(sqrt(fmax(r[7] / Nf - mean_unc * mean_unc, 0.0)), 1e-6);
    double std_e    = fmax(sqrt(fmax(r[9] / Nf - mean_e * mean_e, 0.0)), 1e-6);
    double corr     = cov / (std_unc * std_e + 1e-6);
    double cl       = fmax(0.5 - corr, 0.0);
    double corr_loss = cl * cl;
    double unc_loss = 0.5 * mse_unc + 0.3 * corr_loss + 0.2 * (fmax(-corr, 0.0) * 10.0);

    double unc_bounds = 0.05 * ((r[11] + r[12]) / Nf);

    double mean_gap  = fabs(r[2] / Nf - r[3] / Nf);
    double max_gap   = fmax(1.0 - (r[15] + 1e-6) / (r[16] + 1e-6), 0.0);
    double prange    = r[15] - r[17], trange = r[16] - r[18];
    double range_pen = fmax(1.0 - (prange + 1e-6) / (trange + 1e-6), 0.0);
    double calib = 0.2 * mean_gap + 1.5 * max_gap + 1.0 * range_pen;

    double mp = r[2] / Nf, mt = r[3] / Nf;
    double pstd = sqrt(fmax(r[4] / Nf - mp * mp, 0.0));
    double tstd = sqrt(fmax(r[5] / Nf - mt * mt, 0.0));
    double vr = pstd / (tstd + 1e-8);
    double minvar = ((pstd < 0.5 * tstd) && (tstd > 1e-4)) ? 2.0 * fmax(0.5 - vr, 0.0) : 0.0;

    double bounds_pen = 5.0 * ((r[13] + r[14]) / Nf);

    // bucket5: eff_rank_w = 0.4*1.5 = 0.6 ; eff_mse_w = 0.5*0.85 = 0.425
    double total = 0.425 * mse_loss + 0.6 * rank_loss + 0.35 * unc_loss
                 + unc_bounds + calib + minvar + bounds_pen;

    float tf = (float)total;
    for (int k = 0; k < out_size; ++k) out[k] = tf;
}

// ---------------- launch ----------------
extern "C" void kernel_launch(void* const* d_in, const int* in_sizes, int n_in,
                              void* d_out, int out_size) {
    const float* pr = (const float*)d_in[0];  // predictions
    const float* tg = (const float*)d_in[1];  // targets
    const float* un = (const float*)d_in[2];  // uncertainties
    const float* sn = (const float*)d_in[3];  // snr_values

    init_kernel<<<1, 1>>>();
    reduce_kernel<<<1, 1024>>>(pr, tg, un, sn);
    dim3 grid(NELEM / ITILE, NELEM / JCHUNK);
    rank_kernel<<<grid, ITILE>>>(pr, tg);
    finalize_kernel<<<1, 1>>>((float*)d_out, out_size);
}